// round 16
// baseline (speedup 1.0000x reference)
#include <cuda_runtime.h>
#include <cuda_bf16.h>
#include <math.h>

// Problem constants
#define B_  2
#define S_  2048
#define D_  2048
#define H_  16
#define HD_ 128
#define M_  (B_ * S_)              // 4096
#define TOT_ (B_ * H_ * S_ * HD_)  // 8388608

typedef unsigned long long u64;

// ---------------------------------------------------------------------------
// f32x2 packed-math helpers (PTX sm_100+ family feature, non-'a')
// ---------------------------------------------------------------------------
__device__ __forceinline__ void ffma2(u64& d, u64 a, u64 b) {
    asm("fma.rn.f32x2 %0, %1, %2, %0;" : "+l"(d) : "l"(a), "l"(b));
}
__device__ __forceinline__ void fmul2(u64& d, u64 a) {
    asm("mul.rn.f32x2 %0, %0, %1;" : "+l"(d) : "l"(a));
}
__device__ __forceinline__ u64 pk2(float x, float y) {
    u64 r;
    asm("mov.b64 %0, {%1, %2};" : "=l"(r) : "f"(x), "f"(y));
    return r;
}
__device__ __forceinline__ void upk2(u64 v, float& x, float& y) {
    asm("mov.b64 {%0, %1}, %2;" : "=f"(x), "=f"(y) : "l"(v));
}

// ---------------------------------------------------------------------------
// Scratch (no cudaMalloc allowed)
// ---------------------------------------------------------------------------
__device__ float g_qraw[(size_t)M_ * D_];   // roped Q, [B*S, D]
__device__ float g_kraw[(size_t)M_ * D_];   // roped K, [B*S, D]
__device__ float g_vraw[(size_t)M_ * D_];   // V, [B*S, D]
__device__ float g_Ot[(size_t)M_ * D_];
__device__ float g_invf[64];
__device__ float2 g_cs[(size_t)S_ * 64];    // (cos, sin) per (s, d&63)

// ---------------------------------------------------------------------------
// SGEMM (FFMA2): C[M,N] = A[M,K] @ B[N,K]^T, row-major (R14-proven).
// 128x256 CTA tile, BK=16, 512 threads, 8x8/thread, register prefetch +
// smem double buffer, one sync per k-tile, 16 warps/SM.
// blockIdx.z selects (B, C). do_rope: z in {0,1} applies RoPE in epilogue
// (partner element d^64 fetched from lane tx^8 via shfl; cos/sin from table).
// ---------------------------------------------------------------------------
#define BM 128
#define BN 256
#define BK 16
#define ARW 132            // 128 + 4 pad
#define BRW 260            // 256 + 4 pad
#define GSMEM ((2 * BK * ARW + 2 * BK * BRW) * 4)   // 50176 B

__global__ void __launch_bounds__(512)
gemm_f2(const float* __restrict__ A,
        const float* __restrict__ B0, const float* __restrict__ B1,
        const float* __restrict__ B2,
        float* __restrict__ C0, float* __restrict__ C1, float* __restrict__ C2,
        int Mdim, int Ndim, int Kdim, int do_rope)
{
    extern __shared__ float smem[];
    float* As = smem;                   // [2][BK][ARW]
    float* Bs = smem + 2 * BK * ARW;    // [2][BK][BRW]

    const float* Bw = (blockIdx.z == 0) ? B0 : (blockIdx.z == 1) ? B1 : B2;
    float* C        = (blockIdx.z == 0) ? C0 : (blockIdx.z == 1) ? C1 : C2;

    const int tid = threadIdx.x;
    const int tx = tid & 31;           // lane; 32 n-groups of 8 -> 256
    const int ty = tid >> 5;           // warp; 16 m-groups of 8 -> 128
    const int m0 = blockIdx.y * BM;
    const int n0 = blockIdx.x * BN;

    // staging slots
    const int rowA = tid >> 2;         // 0..127 (A: 1 float4/thread)
    const int c4   = (tid & 3) * 4;    // 0,4,8,12
    const int rowB0 = tid >> 2;        // 0..127 (B slot 0)
    const int rowB1 = rowB0 + 128;     // 128..255 (B slot 1)

    float4 pa, pb0, pb1;

#define LDG_T(ko) do { \
        pa  = *(const float4*)&A[(size_t)(m0 + rowA) * Kdim + (ko) + c4]; \
        pb0 = *(const float4*)&Bw[(size_t)(n0 + rowB0) * Kdim + (ko) + c4]; \
        pb1 = *(const float4*)&Bw[(size_t)(n0 + rowB1) * Kdim + (ko) + c4]; \
    } while (0)

#define STS_T(st) do { \
        As[((st) * BK + c4 + 0) * ARW + rowA] = pa.x; \
        As[((st) * BK + c4 + 1) * ARW + rowA] = pa.y; \
        As[((st) * BK + c4 + 2) * ARW + rowA] = pa.z; \
        As[((st) * BK + c4 + 3) * ARW + rowA] = pa.w; \
        Bs[((st) * BK + c4 + 0) * BRW + rowB0] = pb0.x; \
        Bs[((st) * BK + c4 + 1) * BRW + rowB0] = pb0.y; \
        Bs[((st) * BK + c4 + 2) * BRW + rowB0] = pb0.z; \
        Bs[((st) * BK + c4 + 3) * BRW + rowB0] = pb0.w; \
        Bs[((st) * BK + c4 + 0) * BRW + rowB1] = pb1.x; \
        Bs[((st) * BK + c4 + 1) * BRW + rowB1] = pb1.y; \
        Bs[((st) * BK + c4 + 2) * BRW + rowB1] = pb1.z; \
        Bs[((st) * BK + c4 + 3) * BRW + rowB1] = pb1.w; \
    } while (0)

    // prologue: tile 0 into buffer 0
    LDG_T(0);
    STS_T(0);
    __syncthreads();

    u64 acc2[8][4];
#pragma unroll
    for (int i = 0; i < 8; i++)
#pragma unroll
        for (int j = 0; j < 4; j++) acc2[i][j] = 0ull;

    const int nt = Kdim / BK;
    for (int t = 0; t < nt; t++) {
        const int buf = t & 1;
        if (t + 1 < nt) LDG_T((t + 1) * BK);

#pragma unroll
        for (int kk = 0; kk < BK; kk++) {
            float4 a0 = *(const float4*)&As[(buf * BK + kk) * ARW + ty * 8];
            float4 a1 = *(const float4*)&As[(buf * BK + kk) * ARW + ty * 8 + 4];
            ulonglong2 bp0 =
                *(const ulonglong2*)&Bs[(buf * BK + kk) * BRW + tx * 8];
            ulonglong2 bp1 =
                *(const ulonglong2*)&Bs[(buf * BK + kk) * BRW + tx * 8 + 4];
            u64 bp[4] = {bp0.x, bp0.y, bp1.x, bp1.y};
            u64 ad[8];
            ad[0] = pk2(a0.x, a0.x); ad[1] = pk2(a0.y, a0.y);
            ad[2] = pk2(a0.z, a0.z); ad[3] = pk2(a0.w, a0.w);
            ad[4] = pk2(a1.x, a1.x); ad[5] = pk2(a1.y, a1.y);
            ad[6] = pk2(a1.z, a1.z); ad[7] = pk2(a1.w, a1.w);
#pragma unroll
            for (int i = 0; i < 8; i++)
#pragma unroll
                for (int j = 0; j < 4; j++)
                    ffma2(acc2[i][j], ad[i], bp[j]);
        }

        if (t + 1 < nt) {
            const int nb = (t + 1) & 1;
            STS_T(nb);
            __syncthreads();
        }
    }

    // epilogue
    if (do_rope && blockIdx.z != 2) {
        // RoPE: cols n0+tx*8..+7 all lie in one head; d = (tx&15)*8 + k,
        // partner element (d^64) is held by lane tx^8 at the same k offset.
        const bool hi = (tx & 8) != 0;          // d >= 64 half
        const int j0 = (tx & 7) * 8;            // (d & 63) base
#pragma unroll
        for (int i = 0; i < 8; i++) {
            const int m = m0 + ty * 8 + i;
            const int s = m & (S_ - 1);
            const float2* cst = &g_cs[(size_t)s * 64 + j0];
            u64 res[4];
#pragma unroll
            for (int jj = 0; jj < 4; jj++) {
                u64 mine = acc2[i][jj];
                u64 part = __shfl_xor_sync(0xffffffffu, mine, 8);
                float v0, v1, p0, p1;
                upk2(mine, v0, v1);
                upk2(part, p0, p1);
                float r0 = hi ? p0 : -p0;
                float r1 = hi ? p1 : -p1;
                float2 cs0 = cst[2 * jj];
                float2 cs1 = cst[2 * jj + 1];
                float o0 = fmaf(r0, cs0.y, v0 * cs0.x);
                float o1 = fmaf(r1, cs1.y, v1 * cs1.x);
                res[jj] = pk2(o0, o1);
            }
            size_t r = (size_t)m * Ndim + n0 + tx * 8;
            *(ulonglong2*)&C[r]     = make_ulonglong2(res[0], res[1]);
            *(ulonglong2*)&C[r + 4] = make_ulonglong2(res[2], res[3]);
        }
    } else {
#pragma unroll
        for (int i = 0; i < 8; i++) {
            size_t r = (size_t)(m0 + ty * 8 + i) * Ndim + n0 + tx * 8;
            *(ulonglong2*)&C[r]     = make_ulonglong2(acc2[i][0], acc2[i][1]);
            *(ulonglong2*)&C[r + 4] = make_ulonglong2(acc2[i][2], acc2[i][3]);
        }
    }
#undef LDG_T
#undef STS_T
}

// ---------------------------------------------------------------------------
// RoPE tables: inv_freq (fp64 accuracy) then (cos, sin) per (s, j)
// ---------------------------------------------------------------------------
__global__ void init_rope()
{
    int j = threadIdx.x;
    if (j < 64) g_invf[j] = (float)exp(-(double)j * 0.14391156831212788);
}

__global__ void init_cs()
{
    int idx = blockIdx.x * 256 + threadIdx.x;   // 131072 total
    if (idx >= S_ * 64) return;
    int s = idx >> 6;
    int j = idx & 63;
    float ang = (float)s * g_invf[j];
    float sn, cs;
    sincosf(ang, &sn, &cs);
    g_cs[idx] = make_float2(cs, sn);
}

// ---------------------------------------------------------------------------
// Flash attention, fp32 + FFMA2, causal. 512 threads, Q-tile 128, KV-tile 64.
// Reads Q/K/V directly from [B*S, D] layout (row stride D, head offset h*128).
// Epilogue writes directly into [B*S, D] layout (R9-proven).
// ---------------------------------------------------------------------------
struct SmemAttn {
    float Qs[128][132];  // [k][r], Q^T, scaled
    float Ks[128][68];   // [k][c], K^T
    float Vs[64][128];   // [c][d]
    float Ss[128][68];   // scores / probs
    float mrow[128];
    float lrow[128];
    float corr[128];
};

__global__ void __launch_bounds__(512)
flash_attn(const float* __restrict__ Qg, const float* __restrict__ Kg,
           const float* __restrict__ Vg, float* __restrict__ Ot)
{
    extern __shared__ char smem_raw[];
    SmemAttn& sm = *reinterpret_cast<SmemAttn*>(smem_raw);

    const int tid = threadIdx.x;
    const int tx = tid & 15;
    const int ty = tid >> 4;                 // 0..31
    const int bh = blockIdx.y;
    const int b = bh >> 4, h = bh & 15;
    const int q0 = (gridDim.x - 1 - blockIdx.x) * 128;   // heavy tiles first

    // [B*S, D] layout: row stride D_, head offset h*HD_
    const float* Qb = Qg + ((size_t)b * S_) * D_ + h * HD_;
    const float* Kb = Kg + ((size_t)b * S_) * D_ + h * HD_;
    const float* Vb = Vg + ((size_t)b * S_) * D_ + h * HD_;

    const float scale = 0.08838834764831845f;  // 128^-0.5

    for (int i = tid; i < 128 * 32; i += 512) {
        int r = i >> 5;
        int c4 = (i & 31) * 4;
        float4 v = *(const float4*)&Qb[(size_t)(q0 + r) * D_ + c4];
        sm.Qs[c4 + 0][r] = v.x * scale;
        sm.Qs[c4 + 1][r] = v.y * scale;
        sm.Qs[c4 + 2][r] = v.z * scale;
        sm.Qs[c4 + 3][r] = v.w * scale;
    }
    if (tid < 128) {
        sm.mrow[tid] = -1e30f;
        sm.lrow[tid] = 0.f;
    }

    u64 o2[4][4];
#pragma unroll
    for (int i = 0; i < 4; i++)
#pragma unroll
        for (int j = 0; j < 4; j++) o2[i][j] = 0ull;

    const int ntiles = q0 / 64 + 2;          // covers kv <= q0+127
    for (int kt = 0; kt < ntiles; kt++) {
        const int k0 = kt * 64;

        for (int i = tid; i < 64 * 32; i += 512) {
            int c = i >> 5;
            int c4 = (i & 31) * 4;
            float4 kv4 = *(const float4*)&Kb[(size_t)(k0 + c) * D_ + c4];
            sm.Ks[c4 + 0][c] = kv4.x;
            sm.Ks[c4 + 1][c] = kv4.y;
            sm.Ks[c4 + 2][c] = kv4.z;
            sm.Ks[c4 + 3][c] = kv4.w;
            float4 vv4 = *(const float4*)&Vb[(size_t)(k0 + c) * D_ + c4];
            *(float4*)&sm.Vs[c][c4] = vv4;
        }
        __syncthreads();

        u64 sc2[4][2];
#pragma unroll
        for (int i = 0; i < 4; i++) { sc2[i][0] = 0ull; sc2[i][1] = 0ull; }

#pragma unroll 4
        for (int k = 0; k < 128; k++) {
            float4 qa = *(const float4*)&sm.Qs[k][ty * 4];
            ulonglong2 kp = *(const ulonglong2*)&sm.Ks[k][tx * 4];
            u64 qd[4];
            qd[0] = pk2(qa.x, qa.x); qd[1] = pk2(qa.y, qa.y);
            qd[2] = pk2(qa.z, qa.z); qd[3] = pk2(qa.w, qa.w);
#pragma unroll
            for (int i = 0; i < 4; i++) {
                ffma2(sc2[i][0], qd[i], kp.x);
                ffma2(sc2[i][1], qd[i], kp.y);
            }
        }
#pragma unroll
        for (int i = 0; i < 4; i++) {
            int gq = q0 + ty * 4 + i;
            float s0, s1, s2, s3;
            upk2(sc2[i][0], s0, s1);
            upk2(sc2[i][1], s2, s3);
            int gk = k0 + tx * 4;
            sm.Ss[ty * 4 + i][tx * 4 + 0] = (gk + 0 <= gq) ? s0 : -1e30f;
            sm.Ss[ty * 4 + i][tx * 4 + 1] = (gk + 1 <= gq) ? s1 : -1e30f;
            sm.Ss[ty * 4 + i][tx * 4 + 2] = (gk + 2 <= gq) ? s2 : -1e30f;
            sm.Ss[ty * 4 + i][tx * 4 + 3] = (gk + 3 <= gq) ? s3 : -1e30f;
        }
        __syncthreads();

        {
            int r = tid >> 2;
            int q = tid & 3;
            float mx = -1e30f;
#pragma unroll
            for (int cc = 0; cc < 16; cc++)
                mx = fmaxf(mx, sm.Ss[r][q * 16 + cc]);
            mx = fmaxf(mx, __shfl_xor_sync(0xffffffffu, mx, 1));
            mx = fmaxf(mx, __shfl_xor_sync(0xffffffffu, mx, 2));
            float m_old = sm.mrow[r];
            float m_new = fmaxf(m_old, mx);
            float ssum = 0.f;
#pragma unroll
            for (int cc = 0; cc < 16; cc++) {
                float p = __expf(sm.Ss[r][q * 16 + cc] - m_new);
                sm.Ss[r][q * 16 + cc] = p;
                ssum += p;
            }
            ssum += __shfl_xor_sync(0xffffffffu, ssum, 1);
            ssum += __shfl_xor_sync(0xffffffffu, ssum, 2);
            if (q == 0) {
                float cr = __expf(m_old - m_new);
                sm.lrow[r] = sm.lrow[r] * cr + ssum;
                sm.mrow[r] = m_new;
                sm.corr[r] = cr;
            }
        }
        __syncthreads();

#pragma unroll
        for (int i = 0; i < 4; i++) {
            float cr = sm.corr[ty * 4 + i];
            u64 crd = pk2(cr, cr);
#pragma unroll
            for (int j = 0; j < 4; j++) fmul2(o2[i][j], crd);
        }
#pragma unroll 4
        for (int c = 0; c < 64; c++) {
            ulonglong2 v0 = *(const ulonglong2*)&sm.Vs[c][tx * 8];
            ulonglong2 v1 = *(const ulonglong2*)&sm.Vs[c][tx * 8 + 4];
            u64 vp[4] = {v0.x, v0.y, v1.x, v1.y};
#pragma unroll
            for (int i = 0; i < 4; i++) {
                float p = sm.Ss[ty * 4 + i][c];
                u64 pd = pk2(p, p);
#pragma unroll
                for (int j = 0; j < 4; j++)
                    ffma2(o2[i][j], pd, vp[j]);
            }
        }
        __syncthreads();
    }

    // Normalize and write DIRECTLY into [B*S, D] layout
#pragma unroll
    for (int i = 0; i < 4; i++) {
        float invl = 1.f / sm.lrow[ty * 4 + i];
        float f[8];
        upk2(o2[i][0], f[0], f[1]); upk2(o2[i][1], f[2], f[3]);
        upk2(o2[i][2], f[4], f[5]); upk2(o2[i][3], f[6], f[7]);
        size_t m = (size_t)(b * S_ + q0 + ty * 4 + i);
        size_t off = m * D_ + h * HD_ + tx * 8;
        *(float4*)&Ot[off]     = make_float4(f[0] * invl, f[1] * invl,
                                             f[2] * invl, f[3] * invl);
        *(float4*)&Ot[off + 4] = make_float4(f[4] * invl, f[5] * invl,
                                             f[6] * invl, f[7] * invl);
    }
}

// ---------------------------------------------------------------------------
// Launch
// ---------------------------------------------------------------------------
extern "C" void kernel_launch(void* const* d_in, const int* in_sizes, int n_in,
                              void* d_out, int out_size)
{
    const float* x  = (const float*)d_in[0];
    const float* Wq = (const float*)d_in[1];
    const float* Wk = (const float*)d_in[2];
    const float* Wv = (const float*)d_in[3];
    const float* Wo = (const float*)d_in[4];
    float* out = (float*)d_out;
    (void)in_sizes; (void)n_in; (void)out_size;

    cudaFuncSetAttribute(gemm_f2, cudaFuncAttributeMaxDynamicSharedMemorySize,
                         GSMEM);
    cudaFuncSetAttribute(flash_attn, cudaFuncAttributeMaxDynamicSharedMemorySize,
                         (int)sizeof(SmemAttn));

    init_rope<<<1, 64>>>();
    init_cs<<<(S_ * 64) / 256, 256>>>();

    // Fused QKV projections + RoPE (z selects weight/output; z<2 roped)
    gemm_f2<<<dim3(D_ / BN, M_ / BM, 3), 512, GSMEM>>>(
        x, Wq, Wk, Wv, g_qraw, g_kraw, g_vraw, M_, D_, D_, 1);

    flash_attn<<<dim3(S_ / 128, B_ * H_), 512, sizeof(SmemAttn)>>>(
        g_qraw, g_kraw, g_vraw, g_Ot);

    // Output projection (no rope)
    gemm_f2<<<dim3(D_ / BN, M_ / BM, 1), 512, GSMEM>>>(
        g_Ot, Wo, Wo, Wo, out, out, out, M_, D_, D_, 0);
}

// round 17
// speedup vs baseline: 1.1294x; 1.1294x over previous
#include <cuda_runtime.h>
#include <cuda_bf16.h>
#include <math.h>

// Problem constants
#define B_  2
#define S_  2048
#define D_  2048
#define H_  16
#define HD_ 128
#define M_  (B_ * S_)              // 4096
#define TOT_ (B_ * H_ * S_ * HD_)  // 8388608

typedef unsigned long long u64;

// ---------------------------------------------------------------------------
// f32x2 packed-math helpers (PTX sm_100+ family feature, non-'a')
// ---------------------------------------------------------------------------
__device__ __forceinline__ void ffma2(u64& d, u64 a, u64 b) {
    asm("fma.rn.f32x2 %0, %1, %2, %0;" : "+l"(d) : "l"(a), "l"(b));
}
__device__ __forceinline__ void fmul2(u64& d, u64 a) {
    asm("mul.rn.f32x2 %0, %0, %1;" : "+l"(d) : "l"(a));
}
__device__ __forceinline__ u64 pk2(float x, float y) {
    u64 r;
    asm("mov.b64 %0, {%1, %2};" : "=l"(r) : "f"(x), "f"(y));
    return r;
}
__device__ __forceinline__ void upk2(u64 v, float& x, float& y) {
    asm("mov.b64 {%0, %1}, %2;" : "=f"(x), "=f"(y) : "l"(v));
}

// ---------------------------------------------------------------------------
// Scratch (no cudaMalloc allowed)
// ---------------------------------------------------------------------------
__device__ float g_qraw[(size_t)M_ * D_];
__device__ float g_kraw[(size_t)M_ * D_];
__device__ float g_vraw[(size_t)M_ * D_];
__device__ float g_Q[(size_t)TOT_];
__device__ float g_K[(size_t)TOT_];
__device__ float g_V[(size_t)TOT_];
__device__ float g_Ot[(size_t)M_ * D_];
__device__ float g_invf[64];

// ---------------------------------------------------------------------------
// SGEMM (FFMA2): C[M,N] = A[M,K] @ B[N,K]^T, row-major (R14-proven, frozen).
// 128x256 CTA tile, BK=16, 512 threads, 8x8/thread, register prefetch +
// smem double buffer, one sync per k-tile, 16 warps/SM.
// blockIdx.z selects (B, C) pair for fused QKV.
// ---------------------------------------------------------------------------
#define BM 128
#define BN 256
#define BK 16
#define ARW 132            // 128 + 4 pad
#define BRW 260            // 256 + 4 pad
#define GSMEM ((2 * BK * ARW + 2 * BK * BRW) * 4)   // 50176 B

__global__ void __launch_bounds__(512)
gemm_f2(const float* __restrict__ A,
        const float* __restrict__ B0, const float* __restrict__ B1,
        const float* __restrict__ B2,
        float* __restrict__ C0, float* __restrict__ C1, float* __restrict__ C2,
        int Mdim, int Ndim, int Kdim)
{
    extern __shared__ float smem[];
    float* As = smem;                   // [2][BK][ARW]
    float* Bs = smem + 2 * BK * ARW;    // [2][BK][BRW]

    const float* Bw = (blockIdx.z == 0) ? B0 : (blockIdx.z == 1) ? B1 : B2;
    float* C        = (blockIdx.z == 0) ? C0 : (blockIdx.z == 1) ? C1 : C2;

    const int tid = threadIdx.x;
    const int tx = tid & 31;           // 32 n-groups of 8 -> 256
    const int ty = tid >> 5;           // 16 m-groups of 8 -> 128
    const int m0 = blockIdx.y * BM;
    const int n0 = blockIdx.x * BN;

    const int rowA = tid >> 2;         // 0..127
    const int c4   = (tid & 3) * 4;    // 0,4,8,12
    const int rowB0 = tid >> 2;        // 0..127
    const int rowB1 = rowB0 + 128;     // 128..255

    float4 pa, pb0, pb1;

#define LDG_T(ko) do { \
        pa  = *(const float4*)&A[(size_t)(m0 + rowA) * Kdim + (ko) + c4]; \
        pb0 = *(const float4*)&Bw[(size_t)(n0 + rowB0) * Kdim + (ko) + c4]; \
        pb1 = *(const float4*)&Bw[(size_t)(n0 + rowB1) * Kdim + (ko) + c4]; \
    } while (0)

#define STS_T(st) do { \
        As[((st) * BK + c4 + 0) * ARW + rowA] = pa.x; \
        As[((st) * BK + c4 + 1) * ARW + rowA] = pa.y; \
        As[((st) * BK + c4 + 2) * ARW + rowA] = pa.z; \
        As[((st) * BK + c4 + 3) * ARW + rowA] = pa.w; \
        Bs[((st) * BK + c4 + 0) * BRW + rowB0] = pb0.x; \
        Bs[((st) * BK + c4 + 1) * BRW + rowB0] = pb0.y; \
        Bs[((st) * BK + c4 + 2) * BRW + rowB0] = pb0.z; \
        Bs[((st) * BK + c4 + 3) * BRW + rowB0] = pb0.w; \
        Bs[((st) * BK + c4 + 0) * BRW + rowB1] = pb1.x; \
        Bs[((st) * BK + c4 + 1) * BRW + rowB1] = pb1.y; \
        Bs[((st) * BK + c4 + 2) * BRW + rowB1] = pb1.z; \
        Bs[((st) * BK + c4 + 3) * BRW + rowB1] = pb1.w; \
    } while (0)

    LDG_T(0);
    STS_T(0);
    __syncthreads();

    u64 acc2[8][4];
#pragma unroll
    for (int i = 0; i < 8; i++)
#pragma unroll
        for (int j = 0; j < 4; j++) acc2[i][j] = 0ull;

    const int nt = Kdim / BK;
    for (int t = 0; t < nt; t++) {
        const int buf = t & 1;
        if (t + 1 < nt) LDG_T((t + 1) * BK);

#pragma unroll
        for (int kk = 0; kk < BK; kk++) {
            float4 a0 = *(const float4*)&As[(buf * BK + kk) * ARW + ty * 8];
            float4 a1 = *(const float4*)&As[(buf * BK + kk) * ARW + ty * 8 + 4];
            ulonglong2 bp0 =
                *(const ulonglong2*)&Bs[(buf * BK + kk) * BRW + tx * 8];
            ulonglong2 bp1 =
                *(const ulonglong2*)&Bs[(buf * BK + kk) * BRW + tx * 8 + 4];
            u64 bp[4] = {bp0.x, bp0.y, bp1.x, bp1.y};
            u64 ad[8];
            ad[0] = pk2(a0.x, a0.x); ad[1] = pk2(a0.y, a0.y);
            ad[2] = pk2(a0.z, a0.z); ad[3] = pk2(a0.w, a0.w);
            ad[4] = pk2(a1.x, a1.x); ad[5] = pk2(a1.y, a1.y);
            ad[6] = pk2(a1.z, a1.z); ad[7] = pk2(a1.w, a1.w);
#pragma unroll
            for (int i = 0; i < 8; i++)
#pragma unroll
                for (int j = 0; j < 4; j++)
                    ffma2(acc2[i][j], ad[i], bp[j]);
        }

        if (t + 1 < nt) {
            const int nb = (t + 1) & 1;
            STS_T(nb);
            __syncthreads();
        }
    }

#pragma unroll
    for (int i = 0; i < 8; i++) {
        size_t r = (size_t)(m0 + ty * 8 + i) * Ndim + n0 + tx * 8;
        *(ulonglong2*)&C[r]     = make_ulonglong2(acc2[i][0], acc2[i][1]);
        *(ulonglong2*)&C[r + 4] = make_ulonglong2(acc2[i][2], acc2[i][3]);
    }
#undef LDG_T
#undef STS_T
}

// ---------------------------------------------------------------------------
// RoPE table (fp64 accuracy, tiny)
// ---------------------------------------------------------------------------
__global__ void init_rope()
{
    int j = threadIdx.x;
    if (j < 64) g_invf[j] = (float)exp(-(double)j * 0.14391156831212788);
}

// ---------------------------------------------------------------------------
// RoPE + pack [B,S,H*hd] -> [B,H,S,hd]
// ---------------------------------------------------------------------------
__global__ void rope_pack(const float* __restrict__ qraw,
                          const float* __restrict__ kraw,
                          const float* __restrict__ vraw,
                          float* __restrict__ Q, float* __restrict__ K,
                          float* __restrict__ V)
{
    int i = blockIdx.x * 256 + threadIdx.x;
    if (i >= TOT_) return;
    int d = i & (HD_ - 1);
    int s = (i >> 7) & (S_ - 1);
    int h = (i >> 18) & (H_ - 1);
    int b = i >> 22;

    size_t raw = (size_t)(b * S_ + s) * D_ + h * HD_ + d;
    int dp = (d < 64) ? d + 64 : d - 64;
    size_t rawp = raw + (dp - d);

    float inv = g_invf[d & 63];
    float ang = (float)s * inv;
    float sn, cs;
    sincosf(ang, &sn, &cs);

    float qv = qraw[raw], qp = qraw[rawp];
    float kv = kraw[raw], kp = kraw[rawp];
    float rq = (d < 64) ? -qp : qp;
    float rk = (d < 64) ? -kp : kp;

    Q[i] = fmaf(rq, sn, qv * cs);
    K[i] = fmaf(rk, sn, kv * cs);
    V[i] = vraw[raw];
}

// ---------------------------------------------------------------------------
// Flash attention, fp32 + FFMA2, causal. 512 threads, Q-tile 128, KV-tile 64.
// Register-resident softmax: row state (m, l) lives in registers replicated
// across the owning half-warp; reductions via __shfl_xor over tx bits.
// Per KV tile: 2 block syncs (was 4), no masked-score smem round trip.
// Epilogue writes directly into [B*S, D] layout.
// ---------------------------------------------------------------------------
struct SmemAttn {
    float Qs[128][132];  // [k][r], Q^T, scaled
    float Ks[128][68];   // [k][c], K^T
    float Vs[64][128];   // [c][d]
    float Ss[128][68];   // probs
};

__global__ void __launch_bounds__(512)
flash_attn(const float* __restrict__ Qg, const float* __restrict__ Kg,
           const float* __restrict__ Vg, float* __restrict__ Ot)
{
    extern __shared__ char smem_raw[];
    SmemAttn& sm = *reinterpret_cast<SmemAttn*>(smem_raw);

    const int tid = threadIdx.x;
    const int tx = tid & 15;
    const int ty = tid >> 4;                 // 0..31 (half-warp id)
    const int bh = blockIdx.y;
    const int b = bh >> 4, h = bh & 15;
    const int q0 = (gridDim.x - 1 - blockIdx.x) * 128;   // heavy tiles first

    const float* Qb = Qg + (size_t)bh * S_ * HD_;
    const float* Kb = Kg + (size_t)bh * S_ * HD_;
    const float* Vb = Vg + (size_t)bh * S_ * HD_;

    const float scale = 0.08838834764831845f;  // 128^-0.5

    for (int i = tid; i < 128 * 32; i += 512) {
        int r = i >> 5;
        int c4 = (i & 31) * 4;
        float4 v = *(const float4*)&Qb[(size_t)(q0 + r) * HD_ + c4];
        sm.Qs[c4 + 0][r] = v.x * scale;
        sm.Qs[c4 + 1][r] = v.y * scale;
        sm.Qs[c4 + 2][r] = v.z * scale;
        sm.Qs[c4 + 3][r] = v.w * scale;
    }

    // Per-row softmax state in registers (replicated across the half-warp)
    float m_i[4], l_i[4];
#pragma unroll
    for (int i = 0; i < 4; i++) { m_i[i] = -1e30f; l_i[i] = 0.f; }

    u64 o2[4][4];
#pragma unroll
    for (int i = 0; i < 4; i++)
#pragma unroll
        for (int j = 0; j < 4; j++) o2[i][j] = 0ull;

    const int ntiles = q0 / 64 + 2;          // covers kv <= q0+127
    for (int kt = 0; kt < ntiles; kt++) {
        const int k0 = kt * 64;

        for (int i = tid; i < 64 * 32; i += 512) {
            int c = i >> 5;
            int c4 = (i & 31) * 4;
            float4 kv4 = *(const float4*)&Kb[(size_t)(k0 + c) * HD_ + c4];
            sm.Ks[c4 + 0][c] = kv4.x;
            sm.Ks[c4 + 1][c] = kv4.y;
            sm.Ks[c4 + 2][c] = kv4.z;
            sm.Ks[c4 + 3][c] = kv4.w;
            float4 vv4 = *(const float4*)&Vb[(size_t)(k0 + c) * HD_ + c4];
            *(float4*)&sm.Vs[c][c4] = vv4;
        }
        __syncthreads();

        // Scores: 4 rows (ty*4+i) x 4 cols (tx*4+j) per thread
        u64 sc2[4][2];
#pragma unroll
        for (int i = 0; i < 4; i++) { sc2[i][0] = 0ull; sc2[i][1] = 0ull; }

#pragma unroll 4
        for (int k = 0; k < 128; k++) {
            float4 qa = *(const float4*)&sm.Qs[k][ty * 4];
            ulonglong2 kp = *(const ulonglong2*)&sm.Ks[k][tx * 4];
            u64 qd[4];
            qd[0] = pk2(qa.x, qa.x); qd[1] = pk2(qa.y, qa.y);
            qd[2] = pk2(qa.z, qa.z); qd[3] = pk2(qa.w, qa.w);
#pragma unroll
            for (int i = 0; i < 4; i++) {
                ffma2(sc2[i][0], qd[i], kp.x);
                ffma2(sc2[i][1], qd[i], kp.y);
            }
        }

        // Register-resident masked softmax per row (half-warp reductions)
#pragma unroll
        for (int i = 0; i < 4; i++) {
            const int gq = q0 + ty * 4 + i;
            float s[4];
            upk2(sc2[i][0], s[0], s[1]);
            upk2(sc2[i][1], s[2], s[3]);
            const int gk = k0 + tx * 4;
#pragma unroll
            for (int j = 0; j < 4; j++)
                if (gk + j > gq) s[j] = -1e30f;

            float mx = fmaxf(fmaxf(s[0], s[1]), fmaxf(s[2], s[3]));
            mx = fmaxf(mx, __shfl_xor_sync(0xffffffffu, mx, 1));
            mx = fmaxf(mx, __shfl_xor_sync(0xffffffffu, mx, 2));
            mx = fmaxf(mx, __shfl_xor_sync(0xffffffffu, mx, 4));
            mx = fmaxf(mx, __shfl_xor_sync(0xffffffffu, mx, 8));

            float m_new = fmaxf(m_i[i], mx);
            float p0 = __expf(s[0] - m_new);
            float p1 = __expf(s[1] - m_new);
            float p2 = __expf(s[2] - m_new);
            float p3 = __expf(s[3] - m_new);
            float ss = (p0 + p1) + (p2 + p3);
            ss += __shfl_xor_sync(0xffffffffu, ss, 1);
            ss += __shfl_xor_sync(0xffffffffu, ss, 2);
            ss += __shfl_xor_sync(0xffffffffu, ss, 4);
            ss += __shfl_xor_sync(0xffffffffu, ss, 8);

            float cr = __expf(m_i[i] - m_new);
            l_i[i] = l_i[i] * cr + ss;
            m_i[i] = m_new;

            u64 crd = pk2(cr, cr);
#pragma unroll
            for (int j = 0; j < 4; j++) fmul2(o2[i][j], crd);

            *(float4*)&sm.Ss[ty * 4 + i][tx * 4] = make_float4(p0, p1, p2, p3);
        }
        __syncwarp();     // P rows produced+consumed within the same warp

        // O update: rows ty*4+i, cols tx*8..+7 as 4 f32x2 pairs
#pragma unroll 4
        for (int c = 0; c < 64; c++) {
            ulonglong2 v0 = *(const ulonglong2*)&sm.Vs[c][tx * 8];
            ulonglong2 v1 = *(const ulonglong2*)&sm.Vs[c][tx * 8 + 4];
            u64 vp[4] = {v0.x, v0.y, v1.x, v1.y};
#pragma unroll
            for (int i = 0; i < 4; i++) {
                float p = sm.Ss[ty * 4 + i][c];
                u64 pd = pk2(p, p);
#pragma unroll
                for (int j = 0; j < 4; j++)
                    ffma2(o2[i][j], pd, vp[j]);
            }
        }
        __syncthreads();   // protect Ks/Vs for next tile's load
    }

    // Normalize and write DIRECTLY into [B*S, D] layout
#pragma unroll
    for (int i = 0; i < 4; i++) {
        float invl = 1.f / l_i[i];
        float f[8];
        upk2(o2[i][0], f[0], f[1]); upk2(o2[i][1], f[2], f[3]);
        upk2(o2[i][2], f[4], f[5]); upk2(o2[i][3], f[6], f[7]);
        size_t m = (size_t)(b * S_ + q0 + ty * 4 + i);
        size_t off = m * D_ + h * HD_ + tx * 8;
        *(float4*)&Ot[off]     = make_float4(f[0] * invl, f[1] * invl,
                                             f[2] * invl, f[3] * invl);
        *(float4*)&Ot[off + 4] = make_float4(f[4] * invl, f[5] * invl,
                                             f[6] * invl, f[7] * invl);
    }
}

// ---------------------------------------------------------------------------
// Launch
// ---------------------------------------------------------------------------
extern "C" void kernel_launch(void* const* d_in, const int* in_sizes, int n_in,
                              void* d_out, int out_size)
{
    const float* x  = (const float*)d_in[0];
    const float* Wq = (const float*)d_in[1];
    const float* Wk = (const float*)d_in[2];
    const float* Wv = (const float*)d_in[3];
    const float* Wo = (const float*)d_in[4];
    float* out = (float*)d_out;
    (void)in_sizes; (void)n_in; (void)out_size;

    cudaFuncSetAttribute(gemm_f2, cudaFuncAttributeMaxDynamicSharedMemorySize,
                         GSMEM);
    cudaFuncSetAttribute(flash_attn, cudaFuncAttributeMaxDynamicSharedMemorySize,
                         (int)sizeof(SmemAttn));

    init_rope<<<1, 64>>>();

    // Fused QKV projections: z selects weight/output pair
    gemm_f2<<<dim3(D_ / BN, M_ / BM, 3), 512, GSMEM>>>(
        x, Wq, Wk, Wv, g_qraw, g_kraw, g_vraw, M_, D_, D_);

    rope_pack<<<TOT_ / 256, 256>>>(g_qraw, g_kraw, g_vraw, g_Q, g_K, g_V);

    flash_attn<<<dim3(S_ / 128, B_ * H_), 512, sizeof(SmemAttn)>>>(
        g_Q, g_K, g_V, g_Ot);

    // Output projection (single z)
    gemm_f2<<<dim3(D_ / BN, M_ / BM, 1), 512, GSMEM>>>(
        g_Ot, Wo, Wo, Wo, out, out, out, M_, D_, D_);
}